// round 16
// baseline (speedup 1.0000x reference)
#include <cuda_runtime.h>
#include <cuda_bf16.h>
#include <math.h>

#define B_   4
#define C64  64
#define H_   256
#define W_   256
#define HW_  65536
#define PW_  128
#define PHW_ 16384
#define ST   68   // padded row stride for k4 smem matrices; mult of 4 -> float4-aligned rows

typedef unsigned long long ull;

// ---------------- f32x2 packed helpers ----------------
__device__ __forceinline__ ull pk2(float lo, float hi) {
    ull r;
    asm("mov.b64 %0, {%1, %2};" : "=l"(r) : "f"(lo), "f"(hi));
    return r;
}
__device__ __forceinline__ void fma2(ull& d, ull a, ull b) {
    asm("fma.rn.f32x2 %0, %1, %2, %0;" : "+l"(d) : "l"(a), "l"(b));
}
__device__ __forceinline__ float2 unpk2(ull v) {
    float lo, hi;
    asm("mov.b64 {%0, %1}, %2;" : "=f"(lo), "=f"(hi) : "l"(v));
    return make_float2(lo, hi);
}

// ---------------- scratch (zero-initialized at module load; k4 re-zeros after use) -----
__device__ float g_xh[B_*C64*HW_];
__device__ float g_yh[B_*C64*HW_];
__device__ float g_px[B_*C64*PHW_];
__device__ float g_py[B_*C64*PHW_];
__device__ float g_Cxy[B_*4096];
__device__ float g_Pxx[B_*4096];
__device__ float g_Pyy[B_*4096];
__device__ float g_Pxy[B_*4096];
__device__ float g_M1[B_*4096];
__device__ float g_M2[B_*4096];

// ---------------- K1: depthwise conv + avgpool, 64x64 tile, 4x4 per thread (R6/R9) -----
template<int K>
__device__ __forceinline__ void conv4(const float (*s)[72], const float2* __restrict__ wps,
                                      int rq, int cq, float4 out[4]) {
    const int hoff = 4 - K/2;
    const int base_r = 4*rq + 3 - K/2;
    const int xb = 4*cq;

    ull accA[4], accB[4];
#pragma unroll
    for (int c = 0; c < 4; ++c) { accA[c] = 0ULL; accB[c] = 0ULL; }

    float P[12], Cr[12];
    {
        float4 a = *(const float4*)&s[base_r][xb];
        float4 b = *(const float4*)&s[base_r][xb+4];
        float4 c = *(const float4*)&s[base_r][xb+8];
        P[0]=a.x;P[1]=a.y;P[2]=a.z;P[3]=a.w;P[4]=b.x;P[5]=b.y;P[6]=b.z;P[7]=b.w;
        P[8]=c.x;P[9]=c.y;P[10]=c.z;P[11]=c.w;
    }
#pragma unroll
    for (int m = 1; m <= K+2; ++m) {
        {
            float4 a = *(const float4*)&s[base_r+m][xb];
            float4 b = *(const float4*)&s[base_r+m][xb+4];
            float4 c = *(const float4*)&s[base_r+m][xb+8];
            Cr[0]=a.x;Cr[1]=a.y;Cr[2]=a.z;Cr[3]=a.w;Cr[4]=b.x;Cr[5]=b.y;Cr[6]=b.z;Cr[7]=b.w;
            Cr[8]=c.x;Cr[9]=c.y;Cr[10]=c.z;Cr[11]=c.w;
        }
        ull pv[K+3];
#pragma unroll
        for (int i = 0; i < K+3; ++i) pv[i] = pk2(P[hoff+i], Cr[hoff+i]);
        const int mp = m - 1;
        if (mp <= K-1) {
#pragma unroll
            for (int dx = 0; dx < K; ++dx) {
                ull wp = *(const ull*)&wps[mp*K + dx];
#pragma unroll
                for (int c = 0; c < 4; ++c) fma2(accA[c], wp, pv[dx+c]);
            }
        }
        if (mp >= 2) {
#pragma unroll
            for (int dx = 0; dx < K; ++dx) {
                ull wp = *(const ull*)&wps[(mp-2)*K + dx];
#pragma unroll
                for (int c = 0; c < 4; ++c) fma2(accB[c], wp, pv[dx+c]);
            }
        }
#pragma unroll
        for (int i = 0; i < 12; ++i) P[i] = Cr[i];
    }
    float2 a0 = unpk2(accA[0]), a1 = unpk2(accA[1]), a2 = unpk2(accA[2]), a3 = unpk2(accA[3]);
    float2 b0 = unpk2(accB[0]), b1 = unpk2(accB[1]), b2 = unpk2(accB[2]), b3 = unpk2(accB[3]);
    out[0] = make_float4(a0.x, a1.x, a2.x, a3.x);
    out[1] = make_float4(a0.y, a1.y, a2.y, a3.y);
    out[2] = make_float4(b0.x, b1.x, b2.x, b3.x);
    out[3] = make_float4(b0.y, b1.y, b2.y, b3.y);
}

__global__ __launch_bounds__(256)
void k1_dwconv_pool(const float* __restrict__ x, const float* __restrict__ y,
                    const float* __restrict__ h1w3, const float* __restrict__ h1w5,
                    const float* __restrict__ h1w7,
                    const float* __restrict__ h2w3, const float* __restrict__ h2w5,
                    const float* __restrict__ h2w7) {
    __shared__ float s[70][72];
    __shared__ float2 wps[49];

    const int c = blockIdx.y;
    const int z = blockIdx.z;
    const int b = z >> 1;
    const int which = z & 1;
    const int ty0 = (blockIdx.x >> 2) * 64;
    const int tx0 = (blockIdx.x & 3) * 64;
    const int tid = threadIdx.x;

    const float* src = which ? y : x;
    const float* w3  = which ? h2w3 : h1w3;
    const float* w5  = which ? h2w5 : h1w5;
    const float* w7  = which ? h2w7 : h1w7;
    float* dst  = which ? g_yh : g_xh;
    float* pdst = which ? g_py : g_px;

    const float* wp; int wn;
    if (c < 32)      { wp = w3 + c*9;        wn = 9;  }
    else if (c < 48) { wp = w5 + (c-32)*25;  wn = 25; }
    else             { wp = w7 + (c-48)*49;  wn = 49; }
    if (tid < wn) { float w = wp[tid]; wps[tid] = make_float2(w, w); }

    const float* base = src + (size_t)(b*C64 + c) * HW_;
    for (int i = tid; i < 70*18; i += 256) {
        int r = i / 18, q = i - r*18;
        int gy = ty0 - 3 + r, gx = tx0 - 4 + q*4;
        float4 v = make_float4(0.f, 0.f, 0.f, 0.f);
        if ((unsigned)gy < 256u && (unsigned)gx <= 252u)
            v = *(const float4*)&base[gy*W_ + gx];
        *(float4*)&s[r][q*4] = v;
    }
    __syncthreads();

    const int rq = tid >> 4;
    const int cq = tid & 15;
    float4 o[4];
    if (c < 32)      conv4<3>(s, wps, rq, cq, o);
    else if (c < 48) conv4<5>(s, wps, rq, cq, o);
    else             conv4<7>(s, wps, rq, cq, o);

    float* dplane = dst + (size_t)(b*C64 + c) * HW_;
#pragma unroll
    for (int t = 0; t < 4; ++t)
        *(float4*)&dplane[(ty0 + 4*rq + t)*W_ + tx0 + 4*cq] = o[t];

    {
        const int pr  = tid >> 3;
        const int pc4 = (tid & 7) * 4;
        float4 pv;
        float* e = &pv.x;
#pragma unroll
        for (int d = 0; d < 4; ++d) {
            int pc = pc4 + d;
            e[d] = 0.25f * (s[2*pr+3][2*pc+4] + s[2*pr+3][2*pc+5] +
                            s[2*pr+4][2*pc+4] + s[2*pr+4][2*pc+5]);
        }
        float* pplane = pdst + (size_t)(b*C64 + c) * PHW_;
        *(float4*)&pplane[(ty0/2 + pr)*PW_ + tx0/2 + pc4] = pv;
    }
}

// ---------------- K2 merged: Pxx, Pyy, Pxy in one pass (R9 measured, 61 us) ------------
__global__ __launch_bounds__(256, 1)
void k2_moments() {
    extern __shared__ float sm[];
    float* sx = sm;               // [64][130]
    float* sy = sm + 64*130;
    const int b = blockIdx.y;
    const int tid = threadIdx.x;
    const int q = tid >> 4;
    const int l = tid & 15;
    ull axx[16], ayy[16], axy[16];
#pragma unroll
    for (int u = 0; u < 16; ++u) { axx[u] = 0ULL; ayy[u] = 0ULL; axy[u] = 0ULL; }

    for (int chunk = blockIdx.x; chunk < PHW_/128; chunk += gridDim.x) {
        const int n0 = chunk * 128;
        __syncthreads();
        for (int li = tid; li < 2048; li += 256) {
            int cc = li >> 5, t4 = (li & 31) * 4;
            size_t go = ((size_t)(b*C64 + cc) << 14) + n0 + t4;
            float4 vx = *(const float4*)&g_px[go];
            float4 vy = *(const float4*)&g_py[go];
            *(float2*)&sx[cc*130 + t4]     = make_float2(vx.x, vx.y);
            *(float2*)&sx[cc*130 + t4 + 2] = make_float2(vx.z, vx.w);
            *(float2*)&sy[cc*130 + t4]     = make_float2(vy.x, vy.y);
            *(float2*)&sy[cc*130 + t4 + 2] = make_float2(vy.z, vy.w);
        }
        __syncthreads();
#pragma unroll 2
        for (int t = 0; t < 128; t += 2) {
            ull ax[4], bx[4], ay[4], by[4];
#pragma unroll
            for (int u = 0; u < 4; ++u) {
                ax[u] = *(const ull*)&sx[(q + 16*u)*130 + t];
                bx[u] = *(const ull*)&sx[(l + 16*u)*130 + t];
                ay[u] = *(const ull*)&sy[(q + 16*u)*130 + t];
                by[u] = *(const ull*)&sy[(l + 16*u)*130 + t];
            }
#pragma unroll
            for (int u = 0; u < 4; ++u)
#pragma unroll
                for (int v = 0; v < 4; ++v) {
                    fma2(axx[u*4+v], ax[u], bx[v]);
                    fma2(ayy[u*4+v], ay[u], by[v]);
                    fma2(axy[u*4+v], ax[u], by[v]);
                }
        }
    }
#pragma unroll
    for (int u = 0; u < 4; ++u)
#pragma unroll
        for (int v = 0; v < 4; ++v) {
            float2 fx = unpk2(axx[u*4+v]);
            float2 fy = unpk2(ayy[u*4+v]);
            float2 fz = unpk2(axy[u*4+v]);
            int o = b*4096 + (q+16*u)*64 + (l+16*v);
            atomicAdd(&g_Pxx[o], fx.x + fx.y);
            atomicAdd(&g_Pyy[o], fy.x + fy.y);
            atomicAdd(&g_Pxy[o], fz.x + fz.y);
        }
}

// ---------------- K3: Cxy = x_h @ y_h^T, 4x4 tiles, register double-buffered (R5) ------
__global__ __launch_bounds__(256, 2)
void k3_cxy() {
    extern __shared__ float sm[];
    float* sx = sm;               // [64][130]
    float* sy = sm + 64*130;
    const int b = blockIdx.y;
    const int tid = threadIdx.x;
    const int q = tid >> 4;
    const int l = tid & 15;
    const int cc0 = tid >> 5;
    const int t4  = (tid & 31) * 4;
    ull acc[16];
#pragma unroll
    for (int u = 0; u < 16; ++u) acc[u] = 0ULL;

    const int NCH = HW_/128;
    float4 rx[4], ry[4];
    int chunk = blockIdx.x;
    {
        int n0 = chunk * 128;
#pragma unroll
        for (int k = 0; k < 4; ++k) {
            size_t go = ((size_t)(b*C64 + cc0 + 8*k) << 16) + n0 + t4;
            rx[k] = *(const float4*)&g_xh[go];
            ry[k] = *(const float4*)&g_yh[go];
        }
    }
    while (true) {
        __syncthreads();
#pragma unroll
        for (int k = 0; k < 4; ++k) {
            int cc = cc0 + 8*k;
            *(float2*)&sx[cc*130 + t4]     = make_float2(rx[k].x, rx[k].y);
            *(float2*)&sx[cc*130 + t4 + 2] = make_float2(rx[k].z, rx[k].w);
            *(float2*)&sy[cc*130 + t4]     = make_float2(ry[k].x, ry[k].y);
            *(float2*)&sy[cc*130 + t4 + 2] = make_float2(ry[k].z, ry[k].w);
        }
        __syncthreads();
        const int next = chunk + gridDim.x;
        if (next < NCH) {
            int n0 = next * 128;
#pragma unroll
            for (int k = 0; k < 4; ++k) {
                size_t go = ((size_t)(b*C64 + cc0 + 8*k) << 16) + n0 + t4;
                rx[k] = *(const float4*)&g_xh[go];
                ry[k] = *(const float4*)&g_yh[go];
            }
        }
#pragma unroll 4
        for (int t = 0; t < 128; t += 2) {
            ull ax[4], by[4];
#pragma unroll
            for (int u = 0; u < 4; ++u) {
                ax[u] = *(const ull*)&sx[(q + 16*u)*130 + t];
                by[u] = *(const ull*)&sy[(l + 16*u)*130 + t];
            }
#pragma unroll
            for (int u = 0; u < 4; ++u)
#pragma unroll
                for (int v = 0; v < 4; ++v)
                    fma2(acc[u*4+v], ax[u], by[v]);
        }
        if (next >= NCH) break;
        chunk = next;
    }
#pragma unroll
    for (int u = 0; u < 4; ++u)
#pragma unroll
        for (int v = 0; v < 4; ++v) {
            float2 f = unpk2(acc[u*4+v]);
            atomicAdd(&g_Cxy[b*4096 + (q+16*u)*64 + (l+16*v)], f.x + f.y);
        }
}

// ---------------- K4: per-batch finalize, smem-staged, 512 threads -----
// dynamic smem: 11 matrices x [64][ST] floats (ST=68) = 191,488 B
#define K4_CXY  0
#define K4_PXX  (1*64*ST)
#define K4_PYY  (2*64*ST)
#define K4_PXY  (3*64*ST)
#define K4_KH   (4*64*ST)
#define K4_QL   (5*64*ST)
#define K4_KL   (6*64*ST)
#define K4_VL   (7*64*ST)
#define K4_PROJ (8*64*ST)
#define K4_T2   (9*64*ST)
#define K4_S    (10*64*ST)
#define K4_SMEM ((11*64*ST)*4)

__global__ __launch_bounds__(512)
void k4_finalize(const float* __restrict__ qh, const float* __restrict__ kh,
                 const float* __restrict__ vh, const float* __restrict__ ql,
                 const float* __restrict__ kl, const float* __restrict__ vl,
                 const float* __restrict__ proj,
                 const float* __restrict__ w1, const float* __restrict__ w2,
                 const float* __restrict__ temp) {
    extern __shared__ float dsm[];
    float* sCxy  = dsm + K4_CXY;
    float* sPxx  = dsm + K4_PXX;
    float* sPyy  = dsm + K4_PYY;
    float* sPxy  = dsm + K4_PXY;
    float* skh   = dsm + K4_KH;
    float* sql   = dsm + K4_QL;
    float* skl   = dsm + K4_KL;
    float* svl   = dsm + K4_VL;
    float* sproj = dsm + K4_PROJ;
    float* T2    = dsm + K4_T2;
    float* S     = dsm + K4_S;

    __shared__ float pooled[64], hidden[16], ha[64], nq2[64], nk2[64];
    __shared__ float A[512];
    __shared__ float psum[512];

    const int b = blockIdx.x, tid = threadIdx.x;
    const int c8  = tid >> 3;          // 0..63
    const int j8  = (tid & 7) * 8;     // 0..56

    // stage all operand matrices into smem (padded, float4-aligned rows)
    for (int li = tid; li < 1024; li += 512) {
        int r = li >> 4, c4 = (li & 15) * 4;
        int gsrc = r*64 + c4;
        int dstp = r*ST + c4;
        *(float4*)&sCxy[dstp] = *(const float4*)&g_Cxy[b*4096 + gsrc];
        *(float4*)&sPxx[dstp] = *(const float4*)&g_Pxx[b*4096 + gsrc];
        *(float4*)&sPyy[dstp] = *(const float4*)&g_Pyy[b*4096 + gsrc];
        *(float4*)&sPxy[dstp] = *(const float4*)&g_Pxy[b*4096 + gsrc];
        *(float4*)&skh[dstp]  = *(const float4*)&kh[gsrc];
        *(float4*)&sql[dstp]  = *(const float4*)&ql[gsrc];
        *(float4*)&skl[dstp]  = *(const float4*)&kl[gsrc];
        *(float4*)&svl[dstp]  = *(const float4*)&vl[gsrc];
        *(float4*)&sproj[dstp]= *(const float4*)&proj[gsrc];
    }
    __syncthreads();

    {   // pooled[c] = (qh . Cxy . kh^T)[c,c] / HW  -- 8 threads per c, 8 i's each
        int c = tid & 63, qq = tid >> 6;   // qq: 0..7
        float acc = 0.f;
        for (int i = qq*8; i < qq*8 + 8; ++i) {
            const float* cr = sCxy + i*ST;
            const float* kr = skh + c*ST;
            float s0=0,s1=0,s2=0,s3=0;
            for (int j = 0; j < 64; j += 4) {
                s0 += cr[j  ]*kr[j  ]; s1 += cr[j+1]*kr[j+1];
                s2 += cr[j+2]*kr[j+2]; s3 += cr[j+3]*kr[j+3];
            }
            acc += qh[c*64+i]*(s0+s1+s2+s3);
        }
        psum[tid] = acc;
        __syncthreads();
        if (tid < 64) {
            float a = 0.f;
#pragma unroll
            for (int k = 0; k < 8; ++k) a += psum[tid + 64*k];
            pooled[tid] = a * (1.0f/(float)HW_);
        }
        __syncthreads();
    }
    if (tid < 16) {
        float a = 0.f;
        for (int cc = 0; cc < 64; ++cc) a += w1[tid*64+cc]*pooled[cc];
        hidden[tid] = fmaxf(a, 0.f);
    }
    __syncthreads();
    if (tid < 64) {
        float a = 0.f;
        for (int j = 0; j < 16; ++j) a += w2[tid*16+j]*hidden[j];
        ha[tid] = tanhf(a);
    }
    __syncthreads();

    {   // T2 = ql @ Pxy
        float acc[8];
#pragma unroll
        for (int v = 0; v < 8; ++v) acc[v] = 0.f;
        for (int i = 0; i < 64; ++i) {
            float a = sql[c8*ST+i];
            const float* pr = sPxy + i*ST + j8;
#pragma unroll
            for (int v = 0; v < 8; ++v) acc[v] += a*pr[v];
        }
#pragma unroll
        for (int v = 0; v < 8; ++v) T2[c8*ST+j8+v] = acc[v];
    }
    __syncthreads();
    {   // S = T2 @ kl^T
        float acc[8];
#pragma unroll
        for (int v = 0; v < 8; ++v) acc[v] = 0.f;
        for (int j = 0; j < 64; ++j) {
            float a = T2[c8*ST+j];
#pragma unroll
            for (int v = 0; v < 8; ++v) acc[v] += a*skl[(j8+v)*ST+j];
        }
#pragma unroll
        for (int v = 0; v < 8; ++v) S[c8*ST+j8+v] = acc[v];
    }
    __syncthreads();
    {   // T2 = ql @ Pxx
        float acc[8];
#pragma unroll
        for (int v = 0; v < 8; ++v) acc[v] = 0.f;
        for (int i = 0; i < 64; ++i) {
            float a = sql[c8*ST+i];
            const float* pr = sPxx + i*ST + j8;
#pragma unroll
            for (int v = 0; v < 8; ++v) acc[v] += a*pr[v];
        }
#pragma unroll
        for (int v = 0; v < 8; ++v) T2[c8*ST+j8+v] = acc[v];
    }
    __syncthreads();
    if (tid < 64) {
        float a = 0.f;
        for (int j = 0; j < 64; ++j) a += T2[tid*ST+j]*sql[tid*ST+j];
        nq2[tid] = a;
    }
    __syncthreads();
    {   // T2 = kl @ Pyy
        float acc[8];
#pragma unroll
        for (int v = 0; v < 8; ++v) acc[v] = 0.f;
        for (int i = 0; i < 64; ++i) {
            float a = skl[c8*ST+i];
            const float* pr = sPyy + i*ST + j8;
#pragma unroll
            for (int v = 0; v < 8; ++v) acc[v] += a*pr[v];
        }
#pragma unroll
        for (int v = 0; v < 8; ++v) T2[c8*ST+j8+v] = acc[v];
    }
    __syncthreads();
    if (tid < 64) {
        float a = 0.f;
        for (int j = 0; j < 64; ++j) a += T2[tid*ST+j]*skl[tid*ST+j];
        nk2[tid] = a;
    }
    __syncthreads();

    if (tid < 64) {
        int c = tid, h = c >> 3;
        float dq = fmaxf(sqrtf(nq2[c]), 1e-12f);
        float tt = temp[h];
        float v[8]; float mx = -1e30f;
#pragma unroll
        for (int dd = 0; dd < 8; ++dd) {
            int d = h*8 + dd;
            float dk = fmaxf(sqrtf(nk2[d]), 1e-12f);
            v[dd] = S[c*ST+d] / (dq*dk) * tt;
            mx = fmaxf(mx, v[dd]);
        }
        float sum = 0.f;
#pragma unroll
        for (int dd = 0; dd < 8; ++dd) { v[dd] = expf(v[dd]-mx); sum += v[dd]; }
        float inv = 1.f/sum;
#pragma unroll
        for (int dd = 0; dd < 8; ++dd) A[c*8+dd] = v[dd]*inv;
    }
    __syncthreads();

    {   // S := blockdiag(A) @ vl ; T2 := diag(ha) @ vh
        int h = c8 >> 3;
        float acc[8];
#pragma unroll
        for (int v = 0; v < 8; ++v) acc[v] = 0.f;
#pragma unroll
        for (int dd = 0; dd < 8; ++dd) {
            float a = A[c8*8+dd];
            const float* vr = svl + (h*8+dd)*ST + j8;
#pragma unroll
            for (int v = 0; v < 8; ++v) acc[v] += a*vr[v];
        }
#pragma unroll
        for (int v = 0; v < 8; ++v) S[c8*ST+j8+v] = acc[v];
        float hac = ha[c8];
#pragma unroll
        for (int v = 0; v < 8; ++v) T2[c8*ST+j8+v] = hac*vh[c8*64+j8+v];
    }
    __syncthreads();

    {   // M1 = proj @ T2 ; M2 = proj @ S
        float a1[8], a2[8];
#pragma unroll
        for (int v = 0; v < 8; ++v) { a1[v] = 0.f; a2[v] = 0.f; }
        for (int c = 0; c < 64; ++c) {
            float p = sproj[c8*ST+c];
            const float* u  = T2 + c*ST + j8;
            const float* bm = S  + c*ST + j8;
#pragma unroll
            for (int v = 0; v < 8; ++v) { a1[v] += p*u[v]; a2[v] += p*bm[v]; }
        }
#pragma unroll
        for (int v = 0; v < 8; ++v) {
            g_M1[b*4096 + c8*64 + j8 + v] = a1[v];
            g_M2[b*4096 + c8*64 + j8 + v] = a2[v];
        }
    }

    // re-zero this batch's accumulators for the next graph replay
    {
        float4 z = make_float4(0.f, 0.f, 0.f, 0.f);
#pragma unroll
        for (int t = 0; t < 2; ++t) {
            int off = b*4096 + tid*8 + t*4;
            *(float4*)&g_Cxy[off] = z;
            *(float4*)&g_Pxx[off] = z;
            *(float4*)&g_Pyy[off] = z;
            *(float4*)&g_Pxy[off] = z;
        }
    }
}

// ---------------- K5: out = M1 @ x_h + M2 @ y, 4x4 conflict-free (R4/R9 measured) ------
__global__ __launch_bounds__(256, 2)
void k5_final(const float* __restrict__ y, float* __restrict__ out) {
    extern __shared__ float sm[];
    float* m1 = sm;                 // [64][65]
    float* m2 = sm + 64*65;
    float* sa = sm + 2*64*65;       // x_h chunk [64][132]
    float* sb = sa + 64*132;        // y   chunk [64][132]

    const int b = blockIdx.y;
    const int tid = threadIdx.x;
    const int n0 = blockIdx.x * 128;

    for (int li = tid; li < 4096; li += 256) {
        int o = li >> 6, k = li & 63;
        m1[o*65+k] = g_M1[b*4096 + li];
        m2[o*65+k] = g_M2[b*4096 + li];
    }
    for (int li = tid; li < 2048; li += 256) {
        int cc = li >> 5, t4 = (li & 31) * 4;
        size_t go = ((size_t)(b*C64 + cc) << 16) + n0 + t4;
        *(float4*)&sa[cc*132 + t4] = *(const float4*)&g_xh[go];
        *(float4*)&sb[cc*132 + t4] = *(const float4*)&y[go];
    }
    __syncthreads();

    const int o0 = (tid >> 4) * 4;
    const int l  = tid & 15;
    ull acc[4][4];
#pragma unroll
    for (int u = 0; u < 4; ++u)
#pragma unroll
        for (int v = 0; v < 4; ++v) acc[u][v] = 0ULL;

#pragma unroll 4
    for (int k = 0; k < 64; ++k) {
        ull a1p[4], a2p[4];
#pragma unroll
        for (int u = 0; u < 4; ++u) {
            float a1 = m1[(o0+u)*65 + k];
            float a2 = m2[(o0+u)*65 + k];
            a1p[u] = pk2(a1, a1);
            a2p[u] = pk2(a2, a2);
        }
        ull bx[4], by[4];
#pragma unroll
        for (int v = 0; v < 4; ++v) {
            bx[v] = *(const ull*)&sa[k*132 + 2*l + 32*v];
            by[v] = *(const ull*)&sb[k*132 + 2*l + 32*v];
        }
#pragma unroll
        for (int u = 0; u < 4; ++u)
#pragma unroll
            for (int v = 0; v < 4; ++v) {
                fma2(acc[u][v], a1p[u], bx[v]);
                fma2(acc[u][v], a2p[u], by[v]);
            }
    }
#pragma unroll
    for (int u = 0; u < 4; ++u) {
        float* op = out + (size_t)(b*C64 + o0 + u)*HW_ + n0 + 2*l;
#pragma unroll
        for (int v = 0; v < 4; ++v) {
            float2 f = unpk2(acc[u][v]);
            *(float2*)(op + 32*v) = f;
        }
    }
}

// ---------------- launcher ----------------
extern "C" void kernel_launch(void* const* d_in, const int* in_sizes, int n_in,
                              void* d_out, int out_size) {
    (void)in_sizes; (void)n_in; (void)out_size;
    const float* x      = (const float*)d_in[0];
    const float* y      = (const float*)d_in[1];
    const float* h1w3   = (const float*)d_in[2];
    const float* h1w5   = (const float*)d_in[3];
    const float* h1w7   = (const float*)d_in[4];
    const float* h2w3   = (const float*)d_in[5];
    const float* h2w5   = (const float*)d_in[6];
    const float* h2w7   = (const float*)d_in[7];
    const float* qh_w   = (const float*)d_in[8];
    const float* kh_w   = (const float*)d_in[9];
    const float* vh_w   = (const float*)d_in[10];
    const float* ql_w   = (const float*)d_in[11];
    const float* kl_w   = (const float*)d_in[12];
    const float* vl_w   = (const float*)d_in[13];
    const float* proj_w = (const float*)d_in[14];
    const float* w1     = (const float*)d_in[15];
    const float* w2     = (const float*)d_in[16];
    const float* temp   = (const float*)d_in[17];
    float* out = (float*)d_out;

    const int SMEM_GEMM = 2*64*130*4;               // 66560
    const int SMEM5     = (2*64*65 + 2*64*132)*4;   // 100864
    cudaFuncSetAttribute(k3_cxy,      cudaFuncAttributeMaxDynamicSharedMemorySize, SMEM_GEMM);
    cudaFuncSetAttribute(k2_moments,  cudaFuncAttributeMaxDynamicSharedMemorySize, SMEM_GEMM);
    cudaFuncSetAttribute(k4_finalize, cudaFuncAttributeMaxDynamicSharedMemorySize, K4_SMEM);
    cudaFuncSetAttribute(k5_final,    cudaFuncAttributeMaxDynamicSharedMemorySize, SMEM5);

    // order: k1(0), k2(1), k3(2), k4(3) <- ncu profiles launch index 3, k5(4)
    k1_dwconv_pool<<<dim3(16, 64, 8), 256>>>(x, y, h1w3, h1w5, h1w7, h2w3, h2w5, h2w7);
    k2_moments<<<dim3(37, B_), 256, SMEM_GEMM>>>();
    k3_cxy<<<dim3(74, B_), 256, SMEM_GEMM>>>();
    k4_finalize<<<B_, 512, K4_SMEM>>>(qh_w, kh_w, vh_w, ql_w, kl_w, vl_w, proj_w, w1, w2, temp);
    k5_final<<<dim3(HW_/128, B_), 256, SMEM5>>>(y, out);
}

// round 17
// speedup vs baseline: 1.0008x; 1.0008x over previous
#include <cuda_runtime.h>
#include <cuda_bf16.h>
#include <math.h>

#define B_   4
#define C64  64
#define H_   256
#define W_   256
#define HW_  65536
#define PW_  128
#define PHW_ 16384
#define ST   68   // padded row stride for k4 smem matrices; mult of 4 -> float4-aligned rows

typedef unsigned long long ull;

// ---------------- f32x2 packed helpers ----------------
__device__ __forceinline__ ull pk2(float lo, float hi) {
    ull r;
    asm("mov.b64 %0, {%1, %2};" : "=l"(r) : "f"(lo), "f"(hi));
    return r;
}
__device__ __forceinline__ void fma2(ull& d, ull a, ull b) {
    asm("fma.rn.f32x2 %0, %1, %2, %0;" : "+l"(d) : "l"(a), "l"(b));
}
__device__ __forceinline__ float2 unpk2(ull v) {
    float lo, hi;
    asm("mov.b64 {%0, %1}, %2;" : "=f"(lo), "=f"(hi) : "l"(v));
    return make_float2(lo, hi);
}

// ---------------- scratch (zero-initialized at module load; k4 re-zeros after use) -----
__device__ float g_xh[B_*C64*HW_];
__device__ float g_yh[B_*C64*HW_];
__device__ float g_px[B_*C64*PHW_];
__device__ float g_py[B_*C64*PHW_];
__device__ float g_Cxy[B_*4096];
__device__ float g_Pxx[B_*4096];
__device__ float g_Pyy[B_*4096];
__device__ float g_Pxy[B_*4096];
__device__ float g_M1[B_*4096];
__device__ float g_M2[B_*4096];

// ---------------- K1: depthwise conv + avgpool, 64x64 tile, 4x4 per thread (R6/R9) -----
template<int K>
__device__ __forceinline__ void conv4(const float (*s)[72], const float2* __restrict__ wps,
                                      int rq, int cq, float4 out[4]) {
    const int hoff = 4 - K/2;
    const int base_r = 4*rq + 3 - K/2;
    const int xb = 4*cq;

    ull accA[4], accB[4];
#pragma unroll
    for (int c = 0; c < 4; ++c) { accA[c] = 0ULL; accB[c] = 0ULL; }

    float P[12], Cr[12];
    {
        float4 a = *(const float4*)&s[base_r][xb];
        float4 b = *(const float4*)&s[base_r][xb+4];
        float4 c = *(const float4*)&s[base_r][xb+8];
        P[0]=a.x;P[1]=a.y;P[2]=a.z;P[3]=a.w;P[4]=b.x;P[5]=b.y;P[6]=b.z;P[7]=b.w;
        P[8]=c.x;P[9]=c.y;P[10]=c.z;P[11]=c.w;
    }
#pragma unroll
    for (int m = 1; m <= K+2; ++m) {
        {
            float4 a = *(const float4*)&s[base_r+m][xb];
            float4 b = *(const float4*)&s[base_r+m][xb+4];
            float4 c = *(const float4*)&s[base_r+m][xb+8];
            Cr[0]=a.x;Cr[1]=a.y;Cr[2]=a.z;Cr[3]=a.w;Cr[4]=b.x;Cr[5]=b.y;Cr[6]=b.z;Cr[7]=b.w;
            Cr[8]=c.x;Cr[9]=c.y;Cr[10]=c.z;Cr[11]=c.w;
        }
        ull pv[K+3];
#pragma unroll
        for (int i = 0; i < K+3; ++i) pv[i] = pk2(P[hoff+i], Cr[hoff+i]);
        const int mp = m - 1;
        if (mp <= K-1) {
#pragma unroll
            for (int dx = 0; dx < K; ++dx) {
                ull wp = *(const ull*)&wps[mp*K + dx];
#pragma unroll
                for (int c = 0; c < 4; ++c) fma2(accA[c], wp, pv[dx+c]);
            }
        }
        if (mp >= 2) {
#pragma unroll
            for (int dx = 0; dx < K; ++dx) {
                ull wp = *(const ull*)&wps[(mp-2)*K + dx];
#pragma unroll
                for (int c = 0; c < 4; ++c) fma2(accB[c], wp, pv[dx+c]);
            }
        }
#pragma unroll
        for (int i = 0; i < 12; ++i) P[i] = Cr[i];
    }
    float2 a0 = unpk2(accA[0]), a1 = unpk2(accA[1]), a2 = unpk2(accA[2]), a3 = unpk2(accA[3]);
    float2 b0 = unpk2(accB[0]), b1 = unpk2(accB[1]), b2 = unpk2(accB[2]), b3 = unpk2(accB[3]);
    out[0] = make_float4(a0.x, a1.x, a2.x, a3.x);
    out[1] = make_float4(a0.y, a1.y, a2.y, a3.y);
    out[2] = make_float4(b0.x, b1.x, b2.x, b3.x);
    out[3] = make_float4(b0.y, b1.y, b2.y, b3.y);
}

__global__ __launch_bounds__(256)
void k1_dwconv_pool(const float* __restrict__ x, const float* __restrict__ y,
                    const float* __restrict__ h1w3, const float* __restrict__ h1w5,
                    const float* __restrict__ h1w7,
                    const float* __restrict__ h2w3, const float* __restrict__ h2w5,
                    const float* __restrict__ h2w7) {
    __shared__ float s[70][72];
    __shared__ float2 wps[49];

    const int c = blockIdx.y;
    const int z = blockIdx.z;
    const int b = z >> 1;
    const int which = z & 1;
    const int ty0 = (blockIdx.x >> 2) * 64;
    const int tx0 = (blockIdx.x & 3) * 64;
    const int tid = threadIdx.x;

    const float* src = which ? y : x;
    const float* w3  = which ? h2w3 : h1w3;
    const float* w5  = which ? h2w5 : h1w5;
    const float* w7  = which ? h2w7 : h1w7;
    float* dst  = which ? g_yh : g_xh;
    float* pdst = which ? g_py : g_px;

    const float* wp; int wn;
    if (c < 32)      { wp = w3 + c*9;        wn = 9;  }
    else if (c < 48) { wp = w5 + (c-32)*25;  wn = 25; }
    else             { wp = w7 + (c-48)*49;  wn = 49; }
    if (tid < wn) { float w = wp[tid]; wps[tid] = make_float2(w, w); }

    const float* base = src + (size_t)(b*C64 + c) * HW_;
    for (int i = tid; i < 70*18; i += 256) {
        int r = i / 18, q = i - r*18;
        int gy = ty0 - 3 + r, gx = tx0 - 4 + q*4;
        float4 v = make_float4(0.f, 0.f, 0.f, 0.f);
        if ((unsigned)gy < 256u && (unsigned)gx <= 252u)
            v = *(const float4*)&base[gy*W_ + gx];
        *(float4*)&s[r][q*4] = v;
    }
    __syncthreads();

    const int rq = tid >> 4;
    const int cq = tid & 15;
    float4 o[4];
    if (c < 32)      conv4<3>(s, wps, rq, cq, o);
    else if (c < 48) conv4<5>(s, wps, rq, cq, o);
    else             conv4<7>(s, wps, rq, cq, o);

    float* dplane = dst + (size_t)(b*C64 + c) * HW_;
#pragma unroll
    for (int t = 0; t < 4; ++t)
        *(float4*)&dplane[(ty0 + 4*rq + t)*W_ + tx0 + 4*cq] = o[t];

    {
        const int pr  = tid >> 3;
        const int pc4 = (tid & 7) * 4;
        float4 pv;
        float* e = &pv.x;
#pragma unroll
        for (int d = 0; d < 4; ++d) {
            int pc = pc4 + d;
            e[d] = 0.25f * (s[2*pr+3][2*pc+4] + s[2*pr+3][2*pc+5] +
                            s[2*pr+4][2*pc+4] + s[2*pr+4][2*pc+5]);
        }
        float* pplane = pdst + (size_t)(b*C64 + c) * PHW_;
        *(float4*)&pplane[(ty0/2 + pr)*PW_ + tx0/2 + pc4] = pv;
    }
}

// ---------------- K2 merged: Pxx, Pyy, Pxy in one pass (R9 measured, 61 us) ------------
__global__ __launch_bounds__(256, 1)
void k2_moments() {
    extern __shared__ float sm[];
    float* sx = sm;               // [64][130]
    float* sy = sm + 64*130;
    const int b = blockIdx.y;
    const int tid = threadIdx.x;
    const int q = tid >> 4;
    const int l = tid & 15;
    ull axx[16], ayy[16], axy[16];
#pragma unroll
    for (int u = 0; u < 16; ++u) { axx[u] = 0ULL; ayy[u] = 0ULL; axy[u] = 0ULL; }

    for (int chunk = blockIdx.x; chunk < PHW_/128; chunk += gridDim.x) {
        const int n0 = chunk * 128;
        __syncthreads();
        for (int li = tid; li < 2048; li += 256) {
            int cc = li >> 5, t4 = (li & 31) * 4;
            size_t go = ((size_t)(b*C64 + cc) << 14) + n0 + t4;
            float4 vx = *(const float4*)&g_px[go];
            float4 vy = *(const float4*)&g_py[go];
            *(float2*)&sx[cc*130 + t4]     = make_float2(vx.x, vx.y);
            *(float2*)&sx[cc*130 + t4 + 2] = make_float2(vx.z, vx.w);
            *(float2*)&sy[cc*130 + t4]     = make_float2(vy.x, vy.y);
            *(float2*)&sy[cc*130 + t4 + 2] = make_float2(vy.z, vy.w);
        }
        __syncthreads();
#pragma unroll 2
        for (int t = 0; t < 128; t += 2) {
            ull ax[4], bx[4], ay[4], by[4];
#pragma unroll
            for (int u = 0; u < 4; ++u) {
                ax[u] = *(const ull*)&sx[(q + 16*u)*130 + t];
                bx[u] = *(const ull*)&sx[(l + 16*u)*130 + t];
                ay[u] = *(const ull*)&sy[(q + 16*u)*130 + t];
                by[u] = *(const ull*)&sy[(l + 16*u)*130 + t];
            }
#pragma unroll
            for (int u = 0; u < 4; ++u)
#pragma unroll
                for (int v = 0; v < 4; ++v) {
                    fma2(axx[u*4+v], ax[u], bx[v]);
                    fma2(ayy[u*4+v], ay[u], by[v]);
                    fma2(axy[u*4+v], ax[u], by[v]);
                }
        }
    }
#pragma unroll
    for (int u = 0; u < 4; ++u)
#pragma unroll
        for (int v = 0; v < 4; ++v) {
            float2 fx = unpk2(axx[u*4+v]);
            float2 fy = unpk2(ayy[u*4+v]);
            float2 fz = unpk2(axy[u*4+v]);
            int o = b*4096 + (q+16*u)*64 + (l+16*v);
            atomicAdd(&g_Pxx[o], fx.x + fx.y);
            atomicAdd(&g_Pyy[o], fy.x + fy.y);
            atomicAdd(&g_Pxy[o], fz.x + fz.y);
        }
}

// ---------------- K3: Cxy = x_h @ y_h^T, 4x4 tiles, register double-buffered (R5) ------
__global__ __launch_bounds__(256, 2)
void k3_cxy() {
    extern __shared__ float sm[];
    float* sx = sm;               // [64][130]
    float* sy = sm + 64*130;
    const int b = blockIdx.y;
    const int tid = threadIdx.x;
    const int q = tid >> 4;
    const int l = tid & 15;
    const int cc0 = tid >> 5;
    const int t4  = (tid & 31) * 4;
    ull acc[16];
#pragma unroll
    for (int u = 0; u < 16; ++u) acc[u] = 0ULL;

    const int NCH = HW_/128;
    float4 rx[4], ry[4];
    int chunk = blockIdx.x;
    {
        int n0 = chunk * 128;
#pragma unroll
        for (int k = 0; k < 4; ++k) {
            size_t go = ((size_t)(b*C64 + cc0 + 8*k) << 16) + n0 + t4;
            rx[k] = *(const float4*)&g_xh[go];
            ry[k] = *(const float4*)&g_yh[go];
        }
    }
    while (true) {
        __syncthreads();
#pragma unroll
        for (int k = 0; k < 4; ++k) {
            int cc = cc0 + 8*k;
            *(float2*)&sx[cc*130 + t4]     = make_float2(rx[k].x, rx[k].y);
            *(float2*)&sx[cc*130 + t4 + 2] = make_float2(rx[k].z, rx[k].w);
            *(float2*)&sy[cc*130 + t4]     = make_float2(ry[k].x, ry[k].y);
            *(float2*)&sy[cc*130 + t4 + 2] = make_float2(ry[k].z, ry[k].w);
        }
        __syncthreads();
        const int next = chunk + gridDim.x;
        if (next < NCH) {
            int n0 = next * 128;
#pragma unroll
            for (int k = 0; k < 4; ++k) {
                size_t go = ((size_t)(b*C64 + cc0 + 8*k) << 16) + n0 + t4;
                rx[k] = *(const float4*)&g_xh[go];
                ry[k] = *(const float4*)&g_yh[go];
            }
        }
#pragma unroll 4
        for (int t = 0; t < 128; t += 2) {
            ull ax[4], by[4];
#pragma unroll
            for (int u = 0; u < 4; ++u) {
                ax[u] = *(const ull*)&sx[(q + 16*u)*130 + t];
                by[u] = *(const ull*)&sy[(l + 16*u)*130 + t];
            }
#pragma unroll
            for (int u = 0; u < 4; ++u)
#pragma unroll
                for (int v = 0; v < 4; ++v)
                    fma2(acc[u*4+v], ax[u], by[v]);
        }
        if (next >= NCH) break;
        chunk = next;
    }
#pragma unroll
    for (int u = 0; u < 4; ++u)
#pragma unroll
        for (int v = 0; v < 4; ++v) {
            float2 f = unpk2(acc[u*4+v]);
            atomicAdd(&g_Cxy[b*4096 + (q+16*u)*64 + (l+16*v)], f.x + f.y);
        }
}

// ---------------- K4: per-batch finalize, smem-staged, fused independent stages --------
// dynamic smem: 12 matrices x [64][ST] floats (ST=68) = 208,896 B
#define K4_CXY  0
#define K4_PXX  (1*64*ST)
#define K4_PYY  (2*64*ST)
#define K4_PXY  (3*64*ST)
#define K4_KH   (4*64*ST)
#define K4_QL   (5*64*ST)
#define K4_KL   (6*64*ST)
#define K4_VL   (7*64*ST)
#define K4_PROJ (8*64*ST)
#define K4_VH   (9*64*ST)
#define K4_T2   (10*64*ST)
#define K4_S    (11*64*ST)
#define K4_SMEM ((12*64*ST)*4)

__global__ __launch_bounds__(256)
void k4_finalize(const float* __restrict__ qh, const float* __restrict__ kh,
                 const float* __restrict__ vh, const float* __restrict__ ql,
                 const float* __restrict__ kl, const float* __restrict__ vl,
                 const float* __restrict__ proj,
                 const float* __restrict__ w1, const float* __restrict__ w2,
                 const float* __restrict__ temp) {
    extern __shared__ float dsm[];
    float* sCxy  = dsm + K4_CXY;
    float* sPxx  = dsm + K4_PXX;
    float* sPyy  = dsm + K4_PYY;
    float* sPxy  = dsm + K4_PXY;
    float* skh   = dsm + K4_KH;
    float* sql   = dsm + K4_QL;
    float* skl   = dsm + K4_KL;
    float* svl   = dsm + K4_VL;
    float* sproj = dsm + K4_PROJ;
    float* svh   = dsm + K4_VH;
    float* T2    = dsm + K4_T2;
    float* S     = dsm + K4_S;

    __shared__ float pooled[64], hidden[16], ha[64], nq2[64], nk2[64];
    __shared__ float A[512];
    __shared__ float psumP[256], psumQ[256], psumK[256];

    const int b = blockIdx.x, tid = threadIdx.x;
    const int c4 = tid >> 2;            // 0..63
    const int j0 = (tid & 3) * 16;      // 0..48
    const int ch = tid & 3;             // quadratic-form chunk

    // stage0: stage all operand matrices (padded, float4-aligned rows)
    for (int li = tid; li < 1024; li += 256) {
        int r = li >> 4, cc4 = (li & 15) * 4;
        int gsrc = r*64 + cc4;
        int dstp = r*ST + cc4;
        *(float4*)&sCxy[dstp] = *(const float4*)&g_Cxy[b*4096 + gsrc];
        *(float4*)&sPxx[dstp] = *(const float4*)&g_Pxx[b*4096 + gsrc];
        *(float4*)&sPyy[dstp] = *(const float4*)&g_Pyy[b*4096 + gsrc];
        *(float4*)&sPxy[dstp] = *(const float4*)&g_Pxy[b*4096 + gsrc];
        *(float4*)&skh[dstp]  = *(const float4*)&kh[gsrc];
        *(float4*)&sql[dstp]  = *(const float4*)&ql[gsrc];
        *(float4*)&skl[dstp]  = *(const float4*)&kl[gsrc];
        *(float4*)&svl[dstp]  = *(const float4*)&vl[gsrc];
        *(float4*)&sproj[dstp]= *(const float4*)&proj[gsrc];
        *(float4*)&svh[dstp]  = *(const float4*)&vh[gsrc];
    }
    __syncthreads();

    // stage1: four independent jobs per thread (no syncs between them)
    {   // (a) pooled partial: c = tid&63, qq = tid>>6 -> 16 i's
        int c = tid & 63, qq = tid >> 6;
        float acc = 0.f;
        for (int i = qq*16; i < qq*16 + 16; ++i) {
            const float* cr = sCxy + i*ST;
            const float* kr = skh + c*ST;
            float s0=0,s1=0,s2=0,s3=0;
            for (int j = 0; j < 64; j += 4) {
                s0 += cr[j  ]*kr[j  ]; s1 += cr[j+1]*kr[j+1];
                s2 += cr[j+2]*kr[j+2]; s3 += cr[j+3]*kr[j+3];
            }
            acc += qh[c*64+i]*(s0+s1+s2+s3);
        }
        psumP[tid] = acc;
    }
    {   // (b) T2 = ql @ Pxy
        float acc[16];
#pragma unroll
        for (int v = 0; v < 16; ++v) acc[v] = 0.f;
        for (int i = 0; i < 64; ++i) {
            float a = sql[c4*ST+i];
            const float* pr = sPxy + i*ST + j0;
#pragma unroll
            for (int v = 0; v < 16; ++v) acc[v] += a*pr[v];
        }
#pragma unroll
        for (int v = 0; v < 16; ++v) T2[c4*ST+j0+v] = acc[v];
    }
    {   // (c) nq2 partial: quadratic form ql Pxx ql^T, rows i in chunk
        float acc = 0.f;
        const float* qr = sql + c4*ST;
        for (int i = ch*16; i < ch*16 + 16; ++i) {
            const float* pr = sPxx + i*ST;
            float s0=0,s1=0,s2=0,s3=0;
            for (int j = 0; j < 64; j += 4) {
                s0 += pr[j  ]*qr[j  ]; s1 += pr[j+1]*qr[j+1];
                s2 += pr[j+2]*qr[j+2]; s3 += pr[j+3]*qr[j+3];
            }
            acc += qr[i]*(s0+s1+s2+s3);
        }
        psumQ[tid] = acc;
    }
    {   // (d) nk2 partial: kl Pyy kl^T
        float acc = 0.f;
        const float* kr = skl + c4*ST;
        for (int i = ch*16; i < ch*16 + 16; ++i) {
            const float* pr = sPyy + i*ST;
            float s0=0,s1=0,s2=0,s3=0;
            for (int j = 0; j < 64; j += 4) {
                s0 += pr[j  ]*kr[j  ]; s1 += pr[j+1]*kr[j+1];
                s2 += pr[j+2]*kr[j+2]; s3 += pr[j+3]*kr[j+3];
            }
            acc += kr[i]*(s0+s1+s2+s3);
        }
        psumK[tid] = acc;
    }
    __syncthreads();

    // stage2: S = T2 @ kl^T  +  reductions (tid<64)
    if (tid < 64) {
        pooled[tid] = (psumP[tid]+psumP[tid+64]+psumP[tid+128]+psumP[tid+192]) * (1.0f/(float)HW_);
        nq2[tid] = psumQ[4*tid]+psumQ[4*tid+1]+psumQ[4*tid+2]+psumQ[4*tid+3];
        nk2[tid] = psumK[4*tid]+psumK[4*tid+1]+psumK[4*tid+2]+psumK[4*tid+3];
    }
    {
        float acc[16];
#pragma unroll
        for (int v = 0; v < 16; ++v) acc[v] = 0.f;
        for (int j = 0; j < 64; ++j) {
            float a = T2[c4*ST+j];
#pragma unroll
            for (int v = 0; v < 16; ++v) acc[v] += a*skl[(j0+v)*ST+j];
        }
#pragma unroll
        for (int v = 0; v < 16; ++v) S[c4*ST+j0+v] = acc[v];
    }
    __syncthreads();

    // stage3: hidden (tid<16)  +  softmax A (tid 64..127)
    if (tid < 16) {
        float a = 0.f;
        for (int cc = 0; cc < 64; ++cc) a += w1[tid*64+cc]*pooled[cc];
        hidden[tid] = fmaxf(a, 0.f);
    }
    if (tid >= 64 && tid < 128) {
        int c = tid - 64, h = c >> 3;
        float dq = fmaxf(sqrtf(nq2[c]), 1e-12f);
        float tt = temp[h];
        float v[8]; float mx = -1e30f;
#pragma unroll
        for (int dd = 0; dd < 8; ++dd) {
            int d = h*8 + dd;
            float dk = fmaxf(sqrtf(nk2[d]), 1e-12f);
            v[dd] = S[c*ST+d] / (dq*dk) * tt;
            mx = fmaxf(mx, v[dd]);
        }
        float sum = 0.f;
#pragma unroll
        for (int dd = 0; dd < 8; ++dd) { v[dd] = expf(v[dd]-mx); sum += v[dd]; }
        float inv = 1.f/sum;
#pragma unroll
        for (int dd = 0; dd < 8; ++dd) A[c*8+dd] = v[dd]*inv;
    }
    __syncthreads();

    // stage4: ha (tid<64)  +  Bm = blockdiag(A)@vl into T2 (all threads)
    if (tid < 64) {
        float a = 0.f;
        for (int j = 0; j < 16; ++j) a += w2[tid*16+j]*hidden[j];
        ha[tid] = tanhf(a);
    }
    {
        int h = c4 >> 3;
        float acc[16];
#pragma unroll
        for (int v = 0; v < 16; ++v) acc[v] = 0.f;
#pragma unroll
        for (int dd = 0; dd < 8; ++dd) {
            float a = A[c4*8+dd];
            const float* vr = svl + (h*8+dd)*ST + j0;
#pragma unroll
            for (int v = 0; v < 16; ++v) acc[v] += a*vr[v];
        }
#pragma unroll
        for (int v = 0; v < 16; ++v) T2[c4*ST+j0+v] = acc[v];
    }
    __syncthreads();

    // stage5: M1 = (proj .* ha) @ vh ; M2 = proj @ Bm(T2)  (ha folded into GEMM)
    {
        float a1[16], a2[16];
#pragma unroll
        for (int v = 0; v < 16; ++v) { a1[v] = 0.f; a2[v] = 0.f; }
        for (int c = 0; c < 64; ++c) {
            float p  = sproj[c4*ST+c];
            float p1 = p * ha[c];
            const float* u  = svh + c*ST + j0;
            const float* bm = T2  + c*ST + j0;
#pragma unroll
            for (int v = 0; v < 16; ++v) { a1[v] += p1*u[v]; a2[v] += p*bm[v]; }
        }
#pragma unroll
        for (int v = 0; v < 16; ++v) {
            g_M1[b*4096 + c4*64 + j0 + v] = a1[v];
            g_M2[b*4096 + c4*64 + j0 + v] = a2[v];
        }
    }

    // re-zero this batch's accumulators for the next graph replay
    {
        float4 z = make_float4(0.f, 0.f, 0.f, 0.f);
#pragma unroll
        for (int t = 0; t < 4; ++t) {
            int off = b*4096 + tid*16 + t*4;
            *(float4*)&g_Cxy[off] = z;
            *(float4*)&g_Pxx[off] = z;
            *(float4*)&g_Pyy[off] = z;
            *(float4*)&g_Pxy[off] = z;
        }
    }
}

// ---------------- K5: out = M1 @ x_h + M2 @ y, 4x4 conflict-free (R4/R9 measured) ------
__global__ __launch_bounds__(256, 2)
void k5_final(const float* __restrict__ y, float* __restrict__ out) {
    extern __shared__ float sm[];
    float* m1 = sm;                 // [64][65]
    float* m2 = sm + 64*65;
    float* sa = sm + 2*64*65;       // x_h chunk [64][132]
    float* sb = sa + 64*132;        // y   chunk [64][132]

    const int b = blockIdx.y;
    const int tid = threadIdx.x;
    const int n0 = blockIdx.x * 128;

    for (int li = tid; li < 4096; li += 256) {
        int o = li >> 6, k = li & 63;
        m1[o*65+k] = g_M1[b*4096 + li];
        m2[o*65+k] = g_M2[b*4096 + li];
    }
    for (int li = tid; li < 2048; li += 256) {
        int cc = li >> 5, t4 = (li & 31) * 4;
        size_t go = ((size_t)(b*C64 + cc) << 16) + n0 + t4;
        *(float4*)&sa[cc*132 + t4] = *(const float4*)&g_xh[go];
        *(float4*)&sb[cc*132 + t4] = *(const float4*)&y[go];
    }
    __syncthreads();

    const int o0 = (tid >> 4) * 4;
    const int l  = tid & 15;
    ull acc[4][4];
#pragma unroll
    for (int u = 0; u < 4; ++u)
#pragma unroll
        for (int v = 0; v < 4; ++v) acc[u][v] = 0ULL;

#pragma unroll 4
    for (int k = 0; k < 64; ++k) {
        ull a1p[4], a2p[4];
#pragma unroll
        for (int u = 0; u < 4; ++u) {
            float a1 = m1[(o0+u)*65 + k];
            float a2 = m2[(o0+u)*65 + k];
            a1p[u] = pk2(a1, a1);
            a2p[u] = pk2(a2, a2);
        }
        ull bx[4], by[4];
#pragma unroll
        for (int v = 0; v < 4; ++v) {
            bx[v] = *(const ull*)&sa[k*132 + 2*l + 32*v];
            by[v] = *(const ull*)&sb[k*132 + 2*l + 32*v];
        }
#pragma unroll
        for (int u = 0; u < 4; ++u)
#pragma unroll
            for (int v = 0; v < 4; ++v) {
                fma2(acc[u][v], a1p[u], bx[v]);
                fma2(acc[u][v], a2p[u], by[v]);
            }
    }
#pragma unroll
    for (int u = 0; u < 4; ++u) {
        float* op = out + (size_t)(b*C64 + o0 + u)*HW_ + n0 + 2*l;
#pragma unroll
        for (int v = 0; v < 4; ++v) {
            float2 f = unpk2(acc[u][v]);
            *(float2*)(op + 32*v) = f;
        }
    }
}

// ---------------- launcher ----------------
extern "C" void kernel_launch(void* const* d_in, const int* in_sizes, int n_in,
                              void* d_out, int out_size) {
    (void)in_sizes; (void)n_in; (void)out_size;
    const float* x      = (const float*)d_in[0];
    const float* y      = (const float*)d_in[1];
    const float* h1w3   = (const float*)d_in[2];
    const float* h1w5   = (const float*)d_in[3];
    const float* h1w7   = (const float*)d_in[4];
    const float* h2w3   = (const float*)d_in[5];
    const float* h2w5   = (const float*)d_in[6];
    const float* h2w7   = (const float*)d_in[7];
    const float* qh_w   = (const float*)d_in[8];
    const float* kh_w   = (const float*)d_in[9];
    const float* vh_w   = (const float*)d_in[10];
    const float* ql_w   = (const float*)d_in[11];
    const float* kl_w   = (const float*)d_in[12];
    const float* vl_w   = (const float*)d_in[13];
    const float* proj_w = (const float*)d_in[14];
    const float* w1     = (const float*)d_in[15];
    const float* w2     = (const float*)d_in[16];
    const float* temp   = (const float*)d_in[17];
    float* out = (float*)d_out;

    const int SMEM_GEMM = 2*64*130*4;               // 66560
    const int SMEM5     = (2*64*65 + 2*64*132)*4;   // 100864
    cudaFuncSetAttribute(k3_cxy,      cudaFuncAttributeMaxDynamicSharedMemorySize, SMEM_GEMM);
    cudaFuncSetAttribute(k2_moments,  cudaFuncAttributeMaxDynamicSharedMemorySize, SMEM_GEMM);
    cudaFuncSetAttribute(k4_finalize, cudaFuncAttributeMaxDynamicSharedMemorySize, K4_SMEM);
    cudaFuncSetAttribute(k5_final,    cudaFuncAttributeMaxDynamicSharedMemorySize, SMEM5);

    // order: k1(0), k2(1), k3(2), k4(3) <- ncu profiles launch index 3, k5(4)
    k1_dwconv_pool<<<dim3(16, 64, 8), 256>>>(x, y, h1w3, h1w5, h1w7, h2w3, h2w5, h2w7);
    k2_moments<<<dim3(37, B_), 256, SMEM_GEMM>>>();
    k3_cxy<<<dim3(74, B_), 256, SMEM_GEMM>>>();
    k4_finalize<<<B_, 256, K4_SMEM>>>(qh_w, kh_w, vh_w, ql_w, kl_w, vl_w, proj_w, w1, w2, temp);
    k5_final<<<dim3(HW_/128, B_), 256, SMEM5>>>(y, out);
}